// round 8
// baseline (speedup 1.0000x reference)
#include <cuda_runtime.h>
#include <cuda_bf16.h>
#include <mma.h>
#include <math.h>

using namespace nvcuda;

// Problem constants
#define SQ    1024
#define HSZ   5120
#define NH    128
#define DNOPE 128
#define DROPE 64
#define DVV   128
#define RQ    1536
#define RKV   512
#define DQK   192
#define QD    192
#define KVD   256
#define HCHUNK 32
#define NCHUNK (NH / HCHUNK)

// ---------------- scratch ----------------------------------------------------
__device__ float g_qc  [SQ * RQ];
__device__ float g_qcn [SQ * RQ];
__device__ float g_ckvn[SQ * RKV];
__device__ float g_q   [SQ * NH * QD];                 // tf32, rope applied in place
__device__ float g_kv  [SQ * NH * KVD];                // tf32
__device__ float g_kr  [SQ * DROPE];                   // tf32
__device__ float g_att [SQ * NH * DVV];                // tf32
__device__ float g_sc  [(size_t)HCHUNK * SQ * SQ];     // 134MB scores chunk

// ---------------- cp.async helpers ------------------------------------------
__device__ __forceinline__ void cp_async16(void* smem_dst, const void* gmem_src)
{
    unsigned saddr = (unsigned)__cvta_generic_to_shared(smem_dst);
    asm volatile("cp.async.cg.shared.global [%0], [%1], 16;\n"
                 :: "r"(saddr), "l"(gmem_src));
}
__device__ __forceinline__ void cp_async16_zfill(void* smem_dst, const void* gmem_src, int bytes)
{
    unsigned saddr = (unsigned)__cvta_generic_to_shared(smem_dst);
    asm volatile("cp.async.cg.shared.global [%0], [%1], 16, %2;\n"
                 :: "r"(saddr), "l"(gmem_src), "r"(bytes));
}
__device__ __forceinline__ void cp_commit() { asm volatile("cp.async.commit_group;\n"); }
__device__ __forceinline__ void cp_wait0()  { asm volatile("cp.async.wait_group 0;\n"); }

// ---------------- cp.async double-buffered TF32 wmma GEMM -------------------
// C[M,N] = alpha * A[M,K] @ op(B)
// TB=false: B is [K,N] (NN) ; TB=true: B is [N,K] (NT, A@B^T)
// Dual-source B: k < K1 -> B ; k >= K1 -> B2 (K1 multiple of BK).
// GUARD: zero-fill B loads / predicate C stores for N not divisible by BN.
// CVT_A/CVT_B: round that operand to tf32 in-loop (skip when source already tf32).
// CVT_C: round output to tf32 in epilogue.
#define BM 128
#define BN 128
#define BK 16
#define NTHR 128

#define LDA_S 20    // BK + 4   (A row-major [m][k])
#define LDBN_S 132  // BN + 4   (B NN row-major [k][n])
#define LDBT_S 20   // BK + 4   (B NT as [n][k], col_major frags)

template <bool TB> struct BLay { using type = wmma::row_major; };
template <>        struct BLay<true> { using type = wmma::col_major; };

template <bool TB, bool GUARD, bool CVT_A, bool CVT_B, bool CVT_C>
__global__ __launch_bounds__(NTHR)
void gemm_tf32(const float* __restrict__ A, const float* __restrict__ B,
               const float* __restrict__ B2, float* __restrict__ C,
               int M, int N, int K, int K1,
               int lda, int ldb, int ldb2, int ldc,
               long long sA, long long sB, long long sB2, long long sC,
               float alpha)
{
    A  += (size_t)blockIdx.z * sA;
    B  += (size_t)blockIdx.z * sB;
    B2 += (size_t)blockIdx.z * sB2;
    C  += (size_t)blockIdx.z * sC;

    __shared__ __align__(16) float As[2][BM * LDA_S];
    __shared__ __align__(16) float Bs[2][BM * LDBT_S > BK * LDBN_S ? BM * LDBT_S : BK * LDBN_S];

    const int m0 = blockIdx.y * BM;
    const int n0 = blockIdx.x * BN;
    const int tid  = threadIdx.x;
    const int warp = tid >> 5;
    const int wm = (warp & 1) * 64;    // 2 warps along M
    const int wn = (warp >> 1) * 64;   // 2 warps along N, each 64x64 output

    wmma::fragment<wmma::accumulator, 16, 16, 8, float> acc[4][4];
    #pragma unroll
    for (int i = 0; i < 4; i++)
        #pragma unroll
        for (int j = 0; j < 4; j++)
            wmma::fill_fragment(acc[i][j], 0.0f);

    // issue cp.async copies for K-tile t into stage st
    auto issue_tile = [&](int t, int st) {
        const int k0 = t * BK;
        #pragma unroll
        for (int i = 0; i < 4; i++) {
            int idx = tid + i * NTHR;
            {   // A: 128 rows x 16 k -> 512 x 16B, k-contiguous
                int r = idx >> 2, c = (idx & 3) * 4;
                cp_async16(&As[st][r * LDA_S + c],
                           &A[(size_t)(m0 + r) * lda + (k0 + c)]);
            }
            if (!TB) {  // B NN: 16 k x 128 n, n-contiguous
                int kr = idx >> 5, c = (idx & 31) * 4;
                int gk = k0 + kr;
                int col = n0 + c;
                const float* src = (gk < K1)
                    ? &B [(size_t)gk * ldb + col]
                    : &B2[(size_t)(gk - K1) * ldb2 + col];
                if (GUARD) {
                    int rem = N - col;
                    int bytes = rem >= 4 ? 16 : (rem > 0 ? rem * 4 : 0);
                    cp_async16_zfill(&Bs[st][kr * LDBN_S + c], src, bytes);
                } else {
                    cp_async16(&Bs[st][kr * LDBN_S + c], src);
                }
            } else {    // B NT: 128 n x 16 k, k-contiguous
                int r = idx >> 2, c = (idx & 3) * 4;
                int gk = k0 + c;
                const float* src = (gk < K1)
                    ? &B [(size_t)(n0 + r) * ldb + gk]
                    : &B2[(size_t)(n0 + r) * ldb2 + (gk - K1)];
                cp_async16(&Bs[st][r * LDBT_S + c], src);
            }
        }
        cp_commit();
    };

    auto compute = [&](int st) {
        #pragma unroll
        for (int kk = 0; kk < BK; kk += 8) {
            wmma::fragment<wmma::matrix_a, 16, 16, 8, wmma::precision::tf32, wmma::row_major> af[4];
            #pragma unroll
            for (int i = 0; i < 4; i++) {
                wmma::load_matrix_sync(af[i], &As[st][(wm + 16 * i) * LDA_S + kk], LDA_S);
                if (CVT_A) {
                    #pragma unroll
                    for (int e = 0; e < af[i].num_elements; e++)
                        af[i].x[e] = wmma::__float_to_tf32(af[i].x[e]);
                }
            }
            wmma::fragment<wmma::matrix_b, 16, 16, 8, wmma::precision::tf32,
                           typename BLay<TB>::type> bf[4];
            #pragma unroll
            for (int j = 0; j < 4; j++) {
                if (!TB)
                    wmma::load_matrix_sync(bf[j], &Bs[st][kk * LDBN_S + wn + 16 * j], LDBN_S);
                else
                    wmma::load_matrix_sync(bf[j], &Bs[st][(wn + 16 * j) * LDBT_S + kk], LDBT_S);
                if (CVT_B) {
                    #pragma unroll
                    for (int e = 0; e < bf[j].num_elements; e++)
                        bf[j].x[e] = wmma::__float_to_tf32(bf[j].x[e]);
                }
            }
            #pragma unroll
            for (int i = 0; i < 4; i++)
                #pragma unroll
                for (int j = 0; j < 4; j++)
                    wmma::mma_sync(acc[i][j], af[i], bf[j], acc[i][j]);
        }
    };

    const int ntiles = K / BK;

    issue_tile(0, 0);

    for (int t = 0; t < ntiles; ++t) {
        cp_wait0();
        __syncthreads();
        if (t + 1 < ntiles)
            issue_tile(t + 1, (t + 1) & 1);
        compute(t & 1);
    }

    // epilogue
    #pragma unroll
    for (int i = 0; i < 4; i++)
        #pragma unroll
        for (int j = 0; j < 4; j++) {
            int cn = n0 + wn + 16 * j;
            if (GUARD && cn + 16 > N) continue;
            #pragma unroll
            for (int t = 0; t < acc[i][j].num_elements; t++) {
                float v = acc[i][j].x[t] * alpha;
                acc[i][j].x[t] = CVT_C ? wmma::__float_to_tf32(v) : v;
            }
            wmma::store_matrix_sync(C + (size_t)(m0 + wm + 16 * i) * ldc + cn,
                                    acc[i][j], ldc, wmma::mem_row_major);
        }
}

// ---------------- rmsnorm (tf32-rounded output) ------------------------------
__global__ void rmsnorm_kernel(const float* __restrict__ x, const float* __restrict__ w,
                               float* __restrict__ y, int N, int ldx, int ldy)
{
    x += (size_t)blockIdx.x * ldx;
    y += (size_t)blockIdx.x * ldy;
    __shared__ float sd[256];
    int t = threadIdx.x;
    float s = 0.0f;
    for (int i = t; i < N; i += 256) { float v = x[i]; s += v * v; }
    sd[t] = s; __syncthreads();
    for (int o = 128; o > 0; o >>= 1) { if (t < o) sd[t] += sd[t + o]; __syncthreads(); }
    float r = rsqrtf(sd[0] / (float)N + 1e-6f);
    for (int i = t; i < N; i += 256) y[i] = wmma::__float_to_tf32(x[i] * r * w[i]);
}

// ---------------- rope (tf32-rounded outputs) --------------------------------
__global__ void rope_q_kernel(float* __restrict__ q)
{
    int idx = blockIdx.x * blockDim.x + threadIdx.x;    // SQ*NH*32
    if (idx >= SQ * NH * 32) return;
    int j = idx & 31;
    int h = (idx >> 5) & (NH - 1);
    int s = idx >> 12;
    float* base = q + (size_t)s * (NH * QD) + (size_t)h * QD + DNOPE;
    float inv = powf(10000.0f, -(float)j / 32.0f);
    float ang = (float)s * inv;
    float c = cosf(ang), sn = sinf(ang);
    float x1 = base[j], x2 = base[j + 32];
    base[j]      = wmma::__float_to_tf32(x1 * c - x2 * sn);
    base[j + 32] = wmma::__float_to_tf32(x2 * c + x1 * sn);
}

__global__ void rope_k_kernel(const float* __restrict__ ckv, float* __restrict__ kr)
{
    int idx = blockIdx.x * blockDim.x + threadIdx.x;    // SQ*32
    if (idx >= SQ * 32) return;
    int j = idx & 31;
    int s = idx >> 5;
    const float* base = ckv + (size_t)s * 576 + RKV;
    float inv = powf(10000.0f, -(float)j / 32.0f);
    float ang = (float)s * inv;
    float c = cosf(ang), sn = sinf(ang);
    float x1 = base[j], x2 = base[j + 32];
    kr[(size_t)s * DROPE + j]      = wmma::__float_to_tf32(x1 * c - x2 * sn);
    kr[(size_t)s * DROPE + j + 32] = wmma::__float_to_tf32(x2 * c + x1 * sn);
}

// ---------------- row softmax (tf32-rounded probs) ---------------------------
__global__ void softmax_kernel(float* __restrict__ x, int N)
{
    x += (size_t)blockIdx.x * N;
    __shared__ float sd[256];
    int t = threadIdx.x;
    float m = -1e30f;
    for (int i = t; i < N; i += 256) m = fmaxf(m, x[i]);
    sd[t] = m; __syncthreads();
    for (int o = 128; o > 0; o >>= 1) { if (t < o) sd[t] = fmaxf(sd[t], sd[t + o]); __syncthreads(); }
    m = sd[0]; __syncthreads();
    float s = 0.0f;
    for (int i = t; i < N; i += 256) { float e = expf(x[i] - m); x[i] = e; s += e; }
    sd[t] = s; __syncthreads();
    for (int o = 128; o > 0; o >>= 1) { if (t < o) sd[t] += sd[t + o]; __syncthreads(); }
    float inv = 1.0f / sd[0];
    for (int i = t; i < N; i += 256) x[i] = wmma::__float_to_tf32(x[i] * inv);
}

// ---------------- driver -----------------------------------------------------
extern "C" void kernel_launch(void* const* d_in, const int* in_sizes, int n_in,
                              void* d_out, int out_size)
{
    const float* hidden    = (const float*)d_in[0];
    const float* Wq_c      = (const float*)d_in[1];
    const float* q_norm_w  = (const float*)d_in[2];
    const float* Wq_d      = (const float*)d_in[3];
    const float* Wkv_c     = (const float*)d_in[4];
    const float* kv_norm_w = (const float*)d_in[5];
    const float* Wkv_d     = (const float*)d_in[6];
    const float* Wo        = (const float*)d_in[7];

    float* out   = (float*)d_out;                     // [1024, 5120]
    float* cache = out + (size_t)SQ * HSZ;            // [1024, 576]

    float *p_qc, *p_qcn, *p_ckvn, *p_q, *p_kv, *p_kr, *p_att, *p_sc;
    cudaGetSymbolAddress((void**)&p_qc,  g_qc);
    cudaGetSymbolAddress((void**)&p_qcn, g_qcn);
    cudaGetSymbolAddress((void**)&p_ckvn,g_ckvn);
    cudaGetSymbolAddress((void**)&p_q,   g_q);
    cudaGetSymbolAddress((void**)&p_kv,  g_kv);
    cudaGetSymbolAddress((void**)&p_kr,  g_kr);
    cudaGetSymbolAddress((void**)&p_att, g_att);
    cudaGetSymbolAddress((void**)&p_sc,  g_sc);

    const float scale = 1.0f / sqrtf((float)DQK);

    // 1) q_c = hidden @ Wq_c              [1024,1536]   A fp32 -> cvt both
    gemm_tf32<false,false,true,true,false><<<dim3(RQ / BN, SQ / BM, 1), NTHR>>>(
        hidden, Wq_c, Wq_c, p_qc, SQ, RQ, HSZ, HSZ,
        HSZ, RQ, RQ, RQ, 0, 0, 0, 0, 1.0f);

    // 2) ckv = hidden @ Wkv_c -> cache    [1024,576]  (fp32 output!)
    gemm_tf32<false,true,true,true,false><<<dim3((576 + BN - 1) / BN, SQ / BM, 1), NTHR>>>(
        hidden, Wkv_c, Wkv_c, cache, SQ, 576, HSZ, HSZ,
        HSZ, 576, 576, 576, 0, 0, 0, 0, 1.0f);

    // --- ncu probes: small duplicate GEMMs at launch idx 2 & 3 so a fixed
    //     skip-count profiling window can land on a GEMM. Write-only to g_sc
    //     scratch, which the attention loop fully overwrites afterwards. ---
    gemm_tf32<true,false,false,false,false><<<dim3(1, 8, 1), NTHR>>>(
        p_q, p_kv, p_kr, p_sc, SQ, SQ, DQK, DNOPE,
        NH * QD, NH * KVD, DROPE, SQ, QD, KVD, 0, (long long)SQ * SQ, scale);
    gemm_tf32<false,false,false,true,false><<<dim3(1, 1, 1), NTHR>>>(
        p_att, Wo, Wo, p_sc, SQ, HSZ, NH * DVV, NH * DVV,
        NH * DVV, HSZ, HSZ, HSZ, 0, 0, 0, 0, 1.0f);

    // 3) rmsnorm (tf32 outputs)
    rmsnorm_kernel<<<SQ, 256>>>(p_qc, q_norm_w, p_qcn, RQ, RQ, RQ);
    rmsnorm_kernel<<<SQ, 256>>>(cache, kv_norm_w, p_ckvn, RKV, 576, RKV);

    // 4) q = qn @ Wq_d                    [1024, 24576]  A tf32 already; C->tf32
    gemm_tf32<false,false,false,true,true><<<dim3((NH * QD) / BN, SQ / BM, 1), NTHR>>>(
        p_qcn, Wq_d, Wq_d, p_q, SQ, NH * QD, RQ, RQ,
        RQ, NH * QD, NH * QD, NH * QD, 0, 0, 0, 0, 1.0f);

    // 5) kv = ckvn @ Wkv_d                [1024, 32768]  A tf32; C->tf32
    gemm_tf32<false,false,false,true,true><<<dim3((NH * KVD) / BN, SQ / BM, 1), NTHR>>>(
        p_ckvn, Wkv_d, Wkv_d, p_kv, SQ, NH * KVD, RKV, RKV,
        RKV, NH * KVD, NH * KVD, NH * KVD, 0, 0, 0, 0, 1.0f);

    // 6) rope (tf32 outputs)
    rope_q_kernel<<<(SQ * NH * 32 + 255) / 256, 256>>>(p_q);
    rope_k_kernel<<<(SQ * 32 + 255) / 256, 256>>>(cache, p_kr);

    // 7) attention, 32 heads per chunk — all operands tf32, zero in-loop cvts
    for (int ch = 0; ch < NCHUNK; ch++) {
        int h0 = ch * HCHUNK;

        gemm_tf32<true,false,false,false,false><<<dim3(SQ / BN, SQ / BM, HCHUNK), NTHR>>>(
            p_q + (size_t)h0 * QD,
            p_kv + (size_t)h0 * KVD,
            p_kr,
            p_sc,
            SQ, SQ, DQK, DNOPE,
            NH * QD, NH * KVD, DROPE, SQ,
            QD, KVD, 0, (long long)SQ * SQ, scale);

        softmax_kernel<<<HCHUNK * SQ, 256>>>(p_sc, SQ);

        gemm_tf32<false,false,false,false,true><<<dim3(DVV / BN, SQ / BM, HCHUNK), NTHR>>>(
            p_sc,
            p_kv + (size_t)h0 * KVD + DNOPE,
            p_kv + (size_t)h0 * KVD + DNOPE,
            p_att + (size_t)h0 * DVV,
            SQ, DVV, SQ, SQ,
            SQ, NH * KVD, NH * KVD, NH * DVV,
            (long long)SQ * SQ, KVD, KVD, DVV, 1.0f);
    }

    // 8) out = att @ Wo                   [1024, 5120]  A tf32; fp32 out
    gemm_tf32<false,false,false,true,false><<<dim3(HSZ / BN, SQ / BM, 1), NTHR>>>(
        p_att, Wo, Wo, out, SQ, HSZ, NH * DVV, NH * DVV,
        NH * DVV, HSZ, HSZ, HSZ, 0, 0, 0, 0, 1.0f);
}

// round 13
// speedup vs baseline: 1.0549x; 1.0549x over previous
#include <cuda_runtime.h>
#include <cuda_bf16.h>
#include <mma.h>
#include <math.h>
#include <stdint.h>

using namespace nvcuda;

// Problem constants
#define SQ    1024
#define HSZ   5120
#define NH    128
#define DNOPE 128
#define DROPE 64
#define DVV   128
#define RQ    1536
#define RKV   512
#define DQK   192
#define QD    192
#define KVD   256
#define HCHUNK 32
#define NCHUNK (NH / HCHUNK)

// ---------------- scratch ----------------------------------------------------
__device__ float g_qc  [SQ * RQ];
__device__ float g_qcn [SQ * RQ];
__device__ float g_ckvn[SQ * RKV];
__device__ float g_q   [SQ * NH * QD];                 // tf32, rope in place
__device__ float g_kv  [SQ * NH * KVD];                // tf32
__device__ float g_kr  [SQ * DROPE];                   // tf32
__device__ float g_att [SQ * NH * DVV];                // tf32
__device__ float g_sc  [(size_t)HCHUNK * SQ * SQ];     // 134MB scores chunk

__device__ __forceinline__ float tf32r(float v) { return wmma::__float_to_tf32(v); }

// ---------------- cp.async helpers ------------------------------------------
__device__ __forceinline__ void cp16(void* smem_dst, const void* gmem_src)
{
    unsigned s = (unsigned)__cvta_generic_to_shared(smem_dst);
    asm volatile("cp.async.cg.shared.global [%0], [%1], 16;\n" :: "r"(s), "l"(gmem_src));
}
__device__ __forceinline__ void cp16z(void* smem_dst, const void* gmem_src, int bytes)
{
    unsigned s = (unsigned)__cvta_generic_to_shared(smem_dst);
    asm volatile("cp.async.cg.shared.global [%0], [%1], 16, %2;\n" :: "r"(s), "l"(gmem_src), "r"(bytes));
}
__device__ __forceinline__ void cp_commit() { asm volatile("cp.async.commit_group;\n"); }
template<int W> __device__ __forceinline__ void cp_wait()
{
    asm volatile("cp.async.wait_group %0;\n" :: "n"(W));
}

// ---------------- 3-stage cp.async TF32 wmma GEMM ---------------------------
// C[M,N] = alpha * A[M,K] @ op(B)
// TB=false: B is [K,N] (NN) ; TB=true: B is [N,K] (NT, A@B^T)
// Dual-source B (NT): k < K1 -> B ; k >= K1 -> B2 (K1 multiple of BK).
// B2 is NEVER batch-offset: it is either head-shared (g_kr) or unused.
// GUARD: zero-fill B loads / predicate C stores for N not divisible by BN.
// CVT_A/CVT_B: in-loop tf32 rounding for raw-fp32 operands. CVT_C: round output.
#define BM 128
#define BN 128
#define BK 32
#define NTHR 256
#define NSTAGE 3

#define LDA_S  36   // BK + 4   A [m][k]
#define LDBN_S 132  // BN + 4   B NN [k][n]
#define LDBT_S 36   // BK + 4   B NT [n][k]

#define A_STAGE_B  (BM * LDA_S * 4)                 // 18432 bytes
#define B_STAGE_B  18432                            // max(128*36, 32*132)*4
#define SMEM_TOTAL (NSTAGE * (A_STAGE_B + B_STAGE_B))   // 110592

template <bool TB> struct BLay { using type = wmma::row_major; };
template <>        struct BLay<true> { using type = wmma::col_major; };

template <bool TB, bool GUARD, bool CVT_A, bool CVT_B, bool CVT_C>
__global__ __launch_bounds__(NTHR)
void gemm_tf32(const float* __restrict__ A, const float* __restrict__ B,
               const float* __restrict__ B2, float* __restrict__ C,
               int N, int K, int K1,
               int lda, int ldb, int ldb2, int ldc,
               long long sA, long long sB, long long sC, float alpha)
{
    extern __shared__ __align__(16) char smem[];
    A  += (size_t)blockIdx.z * sA;
    B  += (size_t)blockIdx.z * sB;
    // B2: NO batch offset (head-shared or unused)
    C  += (size_t)blockIdx.z * sC;

    const int m0 = blockIdx.y * BM;
    const int n0 = blockIdx.x * BN;
    const int tid  = threadIdx.x;
    const int warp = tid >> 5;
    const int wm = (warp & 1) * 64;    // 2 warps along M
    const int wn = (warp >> 1) * 32;   // 4 warps along N

    wmma::fragment<wmma::accumulator, 16, 16, 8, float> acc[4][2];
    #pragma unroll
    for (int i = 0; i < 4; i++)
        #pragma unroll
        for (int j = 0; j < 2; j++)
            wmma::fill_fragment(acc[i][j], 0.0f);

    auto a_stage = [&](int st) { return (float*)(smem + st * A_STAGE_B); };
    auto b_stage = [&](int st) { return (float*)(smem + NSTAGE * A_STAGE_B + st * B_STAGE_B); };

    auto issue_tile = [&](int t, int st) {
        const int k0 = t * BK;
        float* As = a_stage(st);
        float* Bs = b_stage(st);
        #pragma unroll
        for (int i = 0; i < 4; i++) {            // A: 128 x 32 -> 1024 x 16B
            int idx = tid + i * NTHR;
            int r = idx >> 3, q = idx & 7;
            cp16(&As[r * LDA_S + q * 4], &A[(size_t)(m0 + r) * lda + k0 + q * 4]);
        }
        if (TB) {                                 // NT: B [n][k], k-contiguous
            bool r2 = (k0 >= K1);
            #pragma unroll
            for (int i = 0; i < 4; i++) {
                int idx = tid + i * NTHR;
                int r = idx >> 3, q = idx & 7;
                const float* src = r2
                    ? &B2[(size_t)(n0 + r) * ldb2 + (k0 - K1) + q * 4]
                    : &B [(size_t)(n0 + r) * ldb  + k0 + q * 4];
                cp16(&Bs[r * LDBT_S + q * 4], src);
            }
        } else {                                  // NN: B [k][n], n-contiguous
            #pragma unroll
            for (int i = 0; i < 4; i++) {
                int idx = tid + i * NTHR;
                int kk = idx >> 5, c = (idx & 31) * 4;
                int col = n0 + c;
                const float* src = &B[(size_t)(k0 + kk) * ldb + col];
                if (GUARD) {
                    int rem = N - col;
                    int bytes = rem >= 4 ? 16 : (rem > 0 ? rem * 4 : 0);
                    cp16z(&Bs[kk * LDBN_S + c], src, bytes);
                } else {
                    cp16(&Bs[kk * LDBN_S + c], src);
                }
            }
        }
        cp_commit();
    };

    auto compute = [&](int st) {
        float* As = a_stage(st);
        float* Bs = b_stage(st);
        #pragma unroll
        for (int kk = 0; kk < BK; kk += 8) {
            wmma::fragment<wmma::matrix_a, 16, 16, 8, wmma::precision::tf32, wmma::row_major> af[4];
            #pragma unroll
            for (int i = 0; i < 4; i++) {
                wmma::load_matrix_sync(af[i], &As[(wm + 16 * i) * LDA_S + kk], LDA_S);
                if (CVT_A) {
                    #pragma unroll
                    for (int e = 0; e < af[i].num_elements; e++)
                        af[i].x[e] = tf32r(af[i].x[e]);
                }
            }
            wmma::fragment<wmma::matrix_b, 16, 16, 8, wmma::precision::tf32,
                           typename BLay<TB>::type> bf[2];
            #pragma unroll
            for (int j = 0; j < 2; j++) {
                if (TB)
                    wmma::load_matrix_sync(bf[j], &Bs[(wn + 16 * j) * LDBT_S + kk], LDBT_S);
                else
                    wmma::load_matrix_sync(bf[j], &Bs[kk * LDBN_S + wn + 16 * j], LDBN_S);
                if (CVT_B) {
                    #pragma unroll
                    for (int e = 0; e < bf[j].num_elements; e++)
                        bf[j].x[e] = tf32r(bf[j].x[e]);
                }
            }
            #pragma unroll
            for (int i = 0; i < 4; i++)
                #pragma unroll
                for (int j = 0; j < 2; j++)
                    wmma::mma_sync(acc[i][j], af[i], bf[j], acc[i][j]);
        }
    };

    const int T = K / BK;

    issue_tile(0, 0);
    if (T > 1) issue_tile(1, 1);

    for (int t = 0; t < T; ++t) {
        if (t + 1 < T) cp_wait<1>();   // newest group (t+1) may stay in flight; t done
        else           cp_wait<0>();
        __syncthreads();               // all warps done with stage (t-1); copies visible
        if (t + 2 < T) issue_tile(t + 2, (t + 2) % NSTAGE);
        compute(t % NSTAGE);
    }

    // epilogue
    #pragma unroll
    for (int i = 0; i < 4; i++)
        #pragma unroll
        for (int j = 0; j < 2; j++) {
            int cn = n0 + wn + 16 * j;
            if (GUARD && cn + 16 > N) continue;
            #pragma unroll
            for (int e = 0; e < acc[i][j].num_elements; e++) {
                float v = acc[i][j].x[e] * alpha;
                acc[i][j].x[e] = CVT_C ? tf32r(v) : v;
            }
            wmma::store_matrix_sync(C + (size_t)(m0 + wm + 16 * i) * ldc + cn,
                                    acc[i][j], ldc, wmma::mem_row_major);
        }
}

// ---------------- rmsnorm (tf32 output) --------------------------------------
__global__ void rmsnorm_kernel(const float* __restrict__ x, const float* __restrict__ w,
                               float* __restrict__ y, int N, int ldx, int ldy)
{
    x += (size_t)blockIdx.x * ldx;
    y += (size_t)blockIdx.x * ldy;
    __shared__ float sd[256];
    int t = threadIdx.x;
    float s = 0.0f;
    for (int i = t; i < N; i += 256) { float v = x[i]; s += v * v; }
    sd[t] = s; __syncthreads();
    for (int o = 128; o > 0; o >>= 1) { if (t < o) sd[t] += sd[t + o]; __syncthreads(); }
    float r = rsqrtf(sd[0] / (float)N + 1e-6f);
    for (int i = t; i < N; i += 256) y[i] = tf32r(x[i] * r * w[i]);
}

// ---------------- rope (tf32 outputs) ----------------------------------------
__global__ void rope_q_kernel(float* __restrict__ q)
{
    int idx = blockIdx.x * blockDim.x + threadIdx.x;    // SQ*NH*32
    if (idx >= SQ * NH * 32) return;
    int j = idx & 31;
    int h = (idx >> 5) & (NH - 1);
    int s = idx >> 12;
    float* base = q + (size_t)s * (NH * QD) + (size_t)h * QD + DNOPE;
    float inv = powf(10000.0f, -(float)j / 32.0f);
    float ang = (float)s * inv;
    float c = cosf(ang), sn = sinf(ang);
    float x1 = base[j], x2 = base[j + 32];
    base[j]      = tf32r(x1 * c - x2 * sn);
    base[j + 32] = tf32r(x2 * c + x1 * sn);
}

__global__ void rope_k_kernel(const float* __restrict__ ckv, float* __restrict__ kr)
{
    int idx = blockIdx.x * blockDim.x + threadIdx.x;    // SQ*32
    if (idx >= SQ * 32) return;
    int j = idx & 31;
    int s = idx >> 5;
    const float* base = ckv + (size_t)s * 576 + RKV;
    float inv = powf(10000.0f, -(float)j / 32.0f);
    float ang = (float)s * inv;
    float c = cosf(ang), sn = sinf(ang);
    float x1 = base[j], x2 = base[j + 32];
    kr[(size_t)s * DROPE + j]      = tf32r(x1 * c - x2 * sn);
    kr[(size_t)s * DROPE + j + 32] = tf32r(x2 * c + x1 * sn);
}

// ---------------- register-resident row softmax (N=1024, 256 thr) -----------
__global__ void softmax_kernel(float* __restrict__ x)
{
    x += (size_t)blockIdx.x * SQ;
    float4* x4 = (float4*)x;
    __shared__ float sd[256];
    int t = threadIdx.x;

    float4 v = x4[t];                             // one float4 per thread
    float m = fmaxf(fmaxf(v.x, v.y), fmaxf(v.z, v.w));
    sd[t] = m; __syncthreads();
    for (int o = 128; o > 0; o >>= 1) { if (t < o) sd[t] = fmaxf(sd[t], sd[t + o]); __syncthreads(); }
    m = sd[0]; __syncthreads();

    v.x = __expf(v.x - m); v.y = __expf(v.y - m);
    v.z = __expf(v.z - m); v.w = __expf(v.w - m);
    float s = v.x + v.y + v.z + v.w;
    sd[t] = s; __syncthreads();
    for (int o = 128; o > 0; o >>= 1) { if (t < o) sd[t] += sd[t + o]; __syncthreads(); }
    float inv = 1.0f / sd[0];

    v.x = tf32r(v.x * inv); v.y = tf32r(v.y * inv);
    v.z = tf32r(v.z * inv); v.w = tf32r(v.w * inv);
    x4[t] = v;
}

// ---------------- driver -----------------------------------------------------
extern "C" void kernel_launch(void* const* d_in, const int* in_sizes, int n_in,
                              void* d_out, int out_size)
{
    const float* hidden    = (const float*)d_in[0];
    const float* Wq_c      = (const float*)d_in[1];
    const float* q_norm_w  = (const float*)d_in[2];
    const float* Wq_d      = (const float*)d_in[3];
    const float* Wkv_c     = (const float*)d_in[4];
    const float* kv_norm_w = (const float*)d_in[5];
    const float* Wkv_d     = (const float*)d_in[6];
    const float* Wo        = (const float*)d_in[7];

    float* out   = (float*)d_out;                     // [1024, 5120]
    float* cache = out + (size_t)SQ * HSZ;            // [1024, 576]

    float *p_qc, *p_qcn, *p_ckvn, *p_q, *p_kv, *p_kr, *p_att, *p_sc;
    cudaGetSymbolAddress((void**)&p_qc,  g_qc);
    cudaGetSymbolAddress((void**)&p_qcn, g_qcn);
    cudaGetSymbolAddress((void**)&p_ckvn,g_ckvn);
    cudaGetSymbolAddress((void**)&p_q,   g_q);
    cudaGetSymbolAddress((void**)&p_kv,  g_kv);
    cudaGetSymbolAddress((void**)&p_kr,  g_kr);
    cudaGetSymbolAddress((void**)&p_att, g_att);
    cudaGetSymbolAddress((void**)&p_sc,  g_sc);

    // raise dynamic smem cap on every instantiation we use
    cudaFuncSetAttribute(gemm_tf32<false,false,true ,true ,false>, cudaFuncAttributeMaxDynamicSharedMemorySize, SMEM_TOTAL);
    cudaFuncSetAttribute(gemm_tf32<false,true ,true ,true ,false>, cudaFuncAttributeMaxDynamicSharedMemorySize, SMEM_TOTAL);
    cudaFuncSetAttribute(gemm_tf32<false,false,false,true ,true >, cudaFuncAttributeMaxDynamicSharedMemorySize, SMEM_TOTAL);
    cudaFuncSetAttribute(gemm_tf32<true ,false,false,false,false>, cudaFuncAttributeMaxDynamicSharedMemorySize, SMEM_TOTAL);
    cudaFuncSetAttribute(gemm_tf32<false,false,false,false,true >, cudaFuncAttributeMaxDynamicSharedMemorySize, SMEM_TOTAL);
    cudaFuncSetAttribute(gemm_tf32<false,false,false,true ,false>, cudaFuncAttributeMaxDynamicSharedMemorySize, SMEM_TOTAL);

    const float scale = 1.0f / sqrtf((float)DQK);

    // 0) q_c = hidden @ Wq_c              [1024,1536]  (NN, cvt A+B)
    gemm_tf32<false,false,true,true,false><<<dim3(RQ / BN, SQ / BM, 1), NTHR, SMEM_TOTAL>>>(
        hidden, Wq_c, Wq_c, p_qc, RQ, HSZ, HSZ,
        HSZ, RQ, RQ, RQ, 0, 0, 0, 1.0f);

    // 1) ckv = hidden @ Wkv_c -> cache    [1024,576]  (NN, guard, fp32 out)
    gemm_tf32<false,true,true,true,false><<<dim3((576 + BN - 1) / BN, SQ / BM, 1), NTHR, SMEM_TOTAL>>>(
        hidden, Wkv_c, Wkv_c, cache, 576, HSZ, HSZ,
        HSZ, 576, 576, 576, 0, 0, 0, 1.0f);

    // 2-3) ncu probes: realistic GEMM shapes, write scratch g_sc (overwritten later)
    gemm_tf32<true,false,false,false,false><<<dim3(SQ / BN, SQ / BM, 2), NTHR, SMEM_TOTAL>>>(
        p_q, p_kv, p_kr, p_sc, SQ, DQK, DNOPE,
        NH * QD, NH * KVD, DROPE, SQ,
        QD, KVD, (long long)SQ * SQ, scale);
    gemm_tf32<false,false,false,true,false><<<dim3(8, 8, 1), NTHR, SMEM_TOTAL>>>(
        p_att, Wo, Wo, p_sc, HSZ, 2048, 2048,
        NH * DVV, HSZ, HSZ, HSZ, 0, 0, 0, 1.0f);

    // 4-5) rmsnorm (tf32 outputs)
    rmsnorm_kernel<<<SQ, 256>>>(p_qc, q_norm_w, p_qcn, RQ, RQ, RQ);
    rmsnorm_kernel<<<SQ, 256>>>(cache, kv_norm_w, p_ckvn, RKV, 576, RKV);

    // 6) q = qn @ Wq_d                    [1024, 24576]  (NN, cvt B, C->tf32)
    gemm_tf32<false,false,false,true,true><<<dim3((NH * QD) / BN, SQ / BM, 1), NTHR, SMEM_TOTAL>>>(
        p_qcn, Wq_d, Wq_d, p_q, NH * QD, RQ, RQ,
        RQ, NH * QD, NH * QD, NH * QD, 0, 0, 0, 1.0f);

    // 7) kv = ckvn @ Wkv_d                [1024, 32768]  (NN, cvt B, C->tf32)
    gemm_tf32<false,false,false,true,true><<<dim3((NH * KVD) / BN, SQ / BM, 1), NTHR, SMEM_TOTAL>>>(
        p_ckvn, Wkv_d, Wkv_d, p_kv, NH * KVD, RKV, RKV,
        RKV, NH * KVD, NH * KVD, NH * KVD, 0, 0, 0, 1.0f);

    // 8-9) rope
    rope_q_kernel<<<(SQ * NH * 32 + 255) / 256, 256>>>(p_q);
    rope_k_kernel<<<(SQ * 32 + 255) / 256, 256>>>(cache, p_kr);

    // 10..) attention, 32 heads per chunk — all tf32, cvt-free mainloops
    for (int ch = 0; ch < NCHUNK; ch++) {
        int h0 = ch * HCHUNK;

        // scores = scale * Q @ [Kn | kr]^T   (NT, dual-source K1=128, B2 unbatched)
        gemm_tf32<true,false,false,false,false><<<dim3(SQ / BN, SQ / BM, HCHUNK), NTHR, SMEM_TOTAL>>>(
            p_q + (size_t)h0 * QD,
            p_kv + (size_t)h0 * KVD,
            p_kr,
            p_sc,
            SQ, DQK, DNOPE,
            NH * QD, NH * KVD, DROPE, SQ,
            QD, KVD, (long long)SQ * SQ, scale);

        softmax_kernel<<<HCHUNK * SQ, 256>>>(p_sc);

        // att = probs @ V   (NN, V is strided slice of g_kv)
        gemm_tf32<false,false,false,false,true><<<dim3(DVV / BN, SQ / BM, HCHUNK), NTHR, SMEM_TOTAL>>>(
            p_sc,
            p_kv + (size_t)h0 * KVD + DNOPE,
            p_kv + (size_t)h0 * KVD + DNOPE,
            p_att + (size_t)h0 * DVV,
            DVV, SQ, SQ,
            SQ, NH * KVD, NH * KVD, NH * DVV,
            (long long)SQ * SQ, KVD, DVV, 1.0f);
    }

    // last) out = att @ Wo                [1024, 5120]  (NN, cvt B, fp32 out)
    gemm_tf32<false,false,false,true,false><<<dim3(HSZ / BN, SQ / BM, 1), NTHR, SMEM_TOTAL>>>(
        p_att, Wo, Wo, out, HSZ, NH * DVV, NH * DVV,
        NH * DVV, HSZ, HSZ, HSZ, 0, 0, 0, 1.0f);
}

// round 14
// speedup vs baseline: 1.1611x; 1.1006x over previous
#include <cuda_runtime.h>
#include <cuda_bf16.h>
#include <mma.h>
#include <math.h>
#include <stdint.h>

using namespace nvcuda;

// Problem constants
#define SQ    1024
#define HSZ   5120
#define NH    128
#define DNOPE 128
#define DROPE 64
#define DVV   128
#define RQ    1536
#define RKV   512
#define DQK   192
#define QD    192
#define KVD   256
#define HCHUNK 32
#define NCHUNK (NH / HCHUNK)

// ---------------- scratch ----------------------------------------------------
__device__ float g_qc  [SQ * RQ];
__device__ float g_qcn [SQ * RQ];
__device__ float g_ckvn[SQ * RKV];
__device__ float g_q   [SQ * NH * QD];                 // tf32, rope in place
__device__ float g_kv  [SQ * NH * KVD];                // tf32
__device__ float g_kr  [SQ * DROPE];                   // tf32
__device__ float g_att [SQ * NH * DVV];                // tf32
__device__ float g_sc  [(size_t)HCHUNK * SQ * SQ];     // 134MB scores chunk

__device__ __forceinline__ float tf32r(float v) { return wmma::__float_to_tf32(v); }

// ---------------- cp.async helpers ------------------------------------------
__device__ __forceinline__ void cp16(void* smem_dst, const void* gmem_src)
{
    unsigned s = (unsigned)__cvta_generic_to_shared(smem_dst);
    asm volatile("cp.async.cg.shared.global [%0], [%1], 16;\n" :: "r"(s), "l"(gmem_src));
}
__device__ __forceinline__ void cp16z(void* smem_dst, const void* gmem_src, int bytes)
{
    unsigned s = (unsigned)__cvta_generic_to_shared(smem_dst);
    asm volatile("cp.async.cg.shared.global [%0], [%1], 16, %2;\n" :: "r"(s), "l"(gmem_src), "r"(bytes));
}
__device__ __forceinline__ void cp_commit() { asm volatile("cp.async.commit_group;\n"); }
template<int W> __device__ __forceinline__ void cp_wait()
{
    asm volatile("cp.async.wait_group %0;\n" :: "n"(W));
}

// ---------------- 3-stage cp.async TF32 wmma GEMM ---------------------------
// C[M,N] = alpha * A[M,K] @ op(B)
// TB=false: B is [K,N] (NN) ; TB=true: B is [N,K] (NT, A@B^T)
// Dual-source B (NT): k < K1 -> B ; k >= K1 -> B2 (K1 multiple of BK).
// B2 is NEVER batch-offset: it is either head-shared (g_kr) or unused.
// GUARD: zero-fill B loads / predicate C stores for N not divisible by BN.
// CVT_A/CVT_B: in-loop tf32 rounding for raw-fp32 operands. CVT_C: round output.
#define BM 128
#define BN 128
#define BK 32
#define NTHR 256
#define NSTAGE 3

#define LDA_S  36   // BK + 4   A [m][k]
#define LDBN_S 132  // BN + 4   B NN [k][n]
#define LDBT_S 36   // BK + 4   B NT [n][k]

#define A_STAGE_B  (BM * LDA_S * 4)                 // 18432 bytes
#define B_STAGE_B  18432                            // max(128*36, 32*132)*4
#define SMEM_TOTAL (NSTAGE * (A_STAGE_B + B_STAGE_B))   // 110592

template <bool TB> struct BLay { using type = wmma::row_major; };
template <>        struct BLay<true> { using type = wmma::col_major; };

template <bool TB, bool GUARD, bool CVT_A, bool CVT_B, bool CVT_C>
__global__ __launch_bounds__(NTHR, 2)   // cap regs at 128 -> 2 blocks (16 warps) per SM
void gemm_tf32(const float* __restrict__ A, const float* __restrict__ B,
               const float* __restrict__ B2, float* __restrict__ C,
               int N, int K, int K1,
               int lda, int ldb, int ldb2, int ldc,
               long long sA, long long sB, long long sC, float alpha)
{
    extern __shared__ __align__(16) char smem[];
    A  += (size_t)blockIdx.z * sA;
    B  += (size_t)blockIdx.z * sB;
    // B2: NO batch offset (head-shared or unused)
    C  += (size_t)blockIdx.z * sC;

    const int m0 = blockIdx.y * BM;
    const int n0 = blockIdx.x * BN;
    const int tid  = threadIdx.x;
    const int warp = tid >> 5;
    const int wm = (warp & 1) * 64;    // 2 warps along M
    const int wn = (warp >> 1) * 32;   // 4 warps along N

    wmma::fragment<wmma::accumulator, 16, 16, 8, float> acc[4][2];
    #pragma unroll
    for (int i = 0; i < 4; i++)
        #pragma unroll
        for (int j = 0; j < 2; j++)
            wmma::fill_fragment(acc[i][j], 0.0f);

    auto a_stage = [&](int st) { return (float*)(smem + st * A_STAGE_B); };
    auto b_stage = [&](int st) { return (float*)(smem + NSTAGE * A_STAGE_B + st * B_STAGE_B); };

    auto issue_tile = [&](int t, int st) {
        const int k0 = t * BK;
        float* As = a_stage(st);
        float* Bs = b_stage(st);
        #pragma unroll
        for (int i = 0; i < 4; i++) {            // A: 128 x 32 -> 1024 x 16B
            int idx = tid + i * NTHR;
            int r = idx >> 3, q = idx & 7;
            cp16(&As[r * LDA_S + q * 4], &A[(size_t)(m0 + r) * lda + k0 + q * 4]);
        }
        if (TB) {                                 // NT: B [n][k], k-contiguous
            bool r2 = (k0 >= K1);
            #pragma unroll
            for (int i = 0; i < 4; i++) {
                int idx = tid + i * NTHR;
                int r = idx >> 3, q = idx & 7;
                const float* src = r2
                    ? &B2[(size_t)(n0 + r) * ldb2 + (k0 - K1) + q * 4]
                    : &B [(size_t)(n0 + r) * ldb  + k0 + q * 4];
                cp16(&Bs[r * LDBT_S + q * 4], src);
            }
        } else {                                  // NN: B [k][n], n-contiguous
            #pragma unroll
            for (int i = 0; i < 4; i++) {
                int idx = tid + i * NTHR;
                int kk = idx >> 5, c = (idx & 31) * 4;
                int col = n0 + c;
                const float* src = &B[(size_t)(k0 + kk) * ldb + col];
                if (GUARD) {
                    int rem = N - col;
                    int bytes = rem >= 4 ? 16 : (rem > 0 ? rem * 4 : 0);
                    cp16z(&Bs[kk * LDBN_S + c], src, bytes);
                } else {
                    cp16(&Bs[kk * LDBN_S + c], src);
                }
            }
        }
        cp_commit();
    };

    auto compute = [&](int st) {
        float* As = a_stage(st);
        float* Bs = b_stage(st);
        #pragma unroll
        for (int kk = 0; kk < BK; kk += 8) {
            wmma::fragment<wmma::matrix_a, 16, 16, 8, wmma::precision::tf32, wmma::row_major> af[4];
            #pragma unroll
            for (int i = 0; i < 4; i++) {
                wmma::load_matrix_sync(af[i], &As[(wm + 16 * i) * LDA_S + kk], LDA_S);
                if (CVT_A) {
                    #pragma unroll
                    for (int e = 0; e < af[i].num_elements; e++)
                        af[i].x[e] = tf32r(af[i].x[e]);
                }
            }
            wmma::fragment<wmma::matrix_b, 16, 16, 8, wmma::precision::tf32,
                           typename BLay<TB>::type> bf[2];
            #pragma unroll
            for (int j = 0; j < 2; j++) {
                if (TB)
                    wmma::load_matrix_sync(bf[j], &Bs[(wn + 16 * j) * LDBT_S + kk], LDBT_S);
                else
                    wmma::load_matrix_sync(bf[j], &Bs[kk * LDBN_S + wn + 16 * j], LDBN_S);
                if (CVT_B) {
                    #pragma unroll
                    for (int e = 0; e < bf[j].num_elements; e++)
                        bf[j].x[e] = tf32r(bf[j].x[e]);
                }
            }
            #pragma unroll
            for (int i = 0; i < 4; i++)
                #pragma unroll
                for (int j = 0; j < 2; j++)
                    wmma::mma_sync(acc[i][j], af[i], bf[j], acc[i][j]);
        }
    };

    const int T = K / BK;

    issue_tile(0, 0);
    if (T > 1) issue_tile(1, 1);

    for (int t = 0; t < T; ++t) {
        if (t + 1 < T) cp_wait<1>();   // newest group (t+1) may stay in flight; t done
        else           cp_wait<0>();
        __syncthreads();               // all warps done with stage (t-1); copies visible
        if (t + 2 < T) issue_tile(t + 2, (t + 2) % NSTAGE);
        compute(t % NSTAGE);
    }

    // epilogue
    #pragma unroll
    for (int i = 0; i < 4; i++)
        #pragma unroll
        for (int j = 0; j < 2; j++) {
            int cn = n0 + wn + 16 * j;
            if (GUARD && cn + 16 > N) continue;
            #pragma unroll
            for (int e = 0; e < acc[i][j].num_elements; e++) {
                float v = acc[i][j].x[e] * alpha;
                acc[i][j].x[e] = CVT_C ? tf32r(v) : v;
            }
            wmma::store_matrix_sync(C + (size_t)(m0 + wm + 16 * i) * ldc + cn,
                                    acc[i][j], ldc, wmma::mem_row_major);
        }
}

// ---------------- rmsnorm (tf32 output) --------------------------------------
__global__ void rmsnorm_kernel(const float* __restrict__ x, const float* __restrict__ w,
                               float* __restrict__ y, int N, int ldx, int ldy)
{
    x += (size_t)blockIdx.x * ldx;
    y += (size_t)blockIdx.x * ldy;
    __shared__ float sd[256];
    int t = threadIdx.x;
    float s = 0.0f;
    for (int i = t; i < N; i += 256) { float v = x[i]; s += v * v; }
    sd[t] = s; __syncthreads();
    for (int o = 128; o > 0; o >>= 1) { if (t < o) sd[t] += sd[t + o]; __syncthreads(); }
    float r = rsqrtf(sd[0] / (float)N + 1e-6f);
    for (int i = t; i < N; i += 256) y[i] = tf32r(x[i] * r * w[i]);
}

// ---------------- rope (tf32 outputs) ----------------------------------------
__global__ void rope_q_kernel(float* __restrict__ q)
{
    int idx = blockIdx.x * blockDim.x + threadIdx.x;    // SQ*NH*32
    if (idx >= SQ * NH * 32) return;
    int j = idx & 31;
    int h = (idx >> 5) & (NH - 1);
    int s = idx >> 12;
    float* base = q + (size_t)s * (NH * QD) + (size_t)h * QD + DNOPE;
    float inv = powf(10000.0f, -(float)j / 32.0f);
    float ang = (float)s * inv;
    float c = cosf(ang), sn = sinf(ang);
    float x1 = base[j], x2 = base[j + 32];
    base[j]      = tf32r(x1 * c - x2 * sn);
    base[j + 32] = tf32r(x2 * c + x1 * sn);
}

__global__ void rope_k_kernel(const float* __restrict__ ckv, float* __restrict__ kr)
{
    int idx = blockIdx.x * blockDim.x + threadIdx.x;    // SQ*32
    if (idx >= SQ * 32) return;
    int j = idx & 31;
    int s = idx >> 5;
    const float* base = ckv + (size_t)s * 576 + RKV;
    float inv = powf(10000.0f, -(float)j / 32.0f);
    float ang = (float)s * inv;
    float c = cosf(ang), sn = sinf(ang);
    float x1 = base[j], x2 = base[j + 32];
    kr[(size_t)s * DROPE + j]      = tf32r(x1 * c - x2 * sn);
    kr[(size_t)s * DROPE + j + 32] = tf32r(x2 * c + x1 * sn);
}

// ---------------- register-resident row softmax (N=1024, 256 thr) -----------
__global__ void softmax_kernel(float* __restrict__ x)
{
    x += (size_t)blockIdx.x * SQ;
    float4* x4 = (float4*)x;
    __shared__ float sd[256];
    int t = threadIdx.x;

    float4 v = x4[t];                             // one float4 per thread
    float m = fmaxf(fmaxf(v.x, v.y), fmaxf(v.z, v.w));
    sd[t] = m; __syncthreads();
    for (int o = 128; o > 0; o >>= 1) { if (t < o) sd[t] = fmaxf(sd[t], sd[t + o]); __syncthreads(); }
    m = sd[0]; __syncthreads();

    v.x = __expf(v.x - m); v.y = __expf(v.y - m);
    v.z = __expf(v.z - m); v.w = __expf(v.w - m);
    float s = v.x + v.y + v.z + v.w;
    sd[t] = s; __syncthreads();
    for (int o = 128; o > 0; o >>= 1) { if (t < o) sd[t] += sd[t + o]; __syncthreads(); }
    float inv = 1.0f / sd[0];

    v.x = tf32r(v.x * inv); v.y = tf32r(v.y * inv);
    v.z = tf32r(v.z * inv); v.w = tf32r(v.w * inv);
    x4[t] = v;
}

// ---------------- driver -----------------------------------------------------
extern "C" void kernel_launch(void* const* d_in, const int* in_sizes, int n_in,
                              void* d_out, int out_size)
{
    const float* hidden    = (const float*)d_in[0];
    const float* Wq_c      = (const float*)d_in[1];
    const float* q_norm_w  = (const float*)d_in[2];
    const float* Wq_d      = (const float*)d_in[3];
    const float* Wkv_c     = (const float*)d_in[4];
    const float* kv_norm_w = (const float*)d_in[5];
    const float* Wkv_d     = (const float*)d_in[6];
    const float* Wo        = (const float*)d_in[7];

    float* out   = (float*)d_out;                     // [1024, 5120]
    float* cache = out + (size_t)SQ * HSZ;            // [1024, 576]

    float *p_qc, *p_qcn, *p_ckvn, *p_q, *p_kv, *p_kr, *p_att, *p_sc;
    cudaGetSymbolAddress((void**)&p_qc,  g_qc);
    cudaGetSymbolAddress((void**)&p_qcn, g_qcn);
    cudaGetSymbolAddress((void**)&p_ckvn,g_ckvn);
    cudaGetSymbolAddress((void**)&p_q,   g_q);
    cudaGetSymbolAddress((void**)&p_kv,  g_kv);
    cudaGetSymbolAddress((void**)&p_kr,  g_kr);
    cudaGetSymbolAddress((void**)&p_att, g_att);
    cudaGetSymbolAddress((void**)&p_sc,  g_sc);

    // raise dynamic smem cap on every instantiation we use
    cudaFuncSetAttribute(gemm_tf32<false,false,true ,true ,false>, cudaFuncAttributeMaxDynamicSharedMemorySize, SMEM_TOTAL);
    cudaFuncSetAttribute(gemm_tf32<false,true ,true ,true ,false>, cudaFuncAttributeMaxDynamicSharedMemorySize, SMEM_TOTAL);
    cudaFuncSetAttribute(gemm_tf32<false,false,false,true ,true >, cudaFuncAttributeMaxDynamicSharedMemorySize, SMEM_TOTAL);
    cudaFuncSetAttribute(gemm_tf32<true ,false,false,false,false>, cudaFuncAttributeMaxDynamicSharedMemorySize, SMEM_TOTAL);
    cudaFuncSetAttribute(gemm_tf32<false,false,false,false,true >, cudaFuncAttributeMaxDynamicSharedMemorySize, SMEM_TOTAL);
    cudaFuncSetAttribute(gemm_tf32<false,false,false,true ,false>, cudaFuncAttributeMaxDynamicSharedMemorySize, SMEM_TOTAL);

    const float scale = 1.0f / sqrtf((float)DQK);

    // 0) q_c = hidden @ Wq_c              [1024,1536]  (NN, cvt A+B)
    gemm_tf32<false,false,true,true,false><<<dim3(RQ / BN, SQ / BM, 1), NTHR, SMEM_TOTAL>>>(
        hidden, Wq_c, Wq_c, p_qc, RQ, HSZ, HSZ,
        HSZ, RQ, RQ, RQ, 0, 0, 0, 1.0f);

    // 1) ckv = hidden @ Wkv_c -> cache    [1024,576]  (NN, guard, fp32 out)
    gemm_tf32<false,true,true,true,false><<<dim3((576 + BN - 1) / BN, SQ / BM, 1), NTHR, SMEM_TOTAL>>>(
        hidden, Wkv_c, Wkv_c, cache, 576, HSZ, HSZ,
        HSZ, 576, 576, 576, 0, 0, 0, 1.0f);

    // 2-3) rmsnorm (tf32 outputs)
    rmsnorm_kernel<<<SQ, 256>>>(p_qc, q_norm_w, p_qcn, RQ, RQ, RQ);
    rmsnorm_kernel<<<SQ, 256>>>(cache, kv_norm_w, p_ckvn, RKV, 576, RKV);

    // 4) q = qn @ Wq_d                    [1024, 24576]  (NN, cvt B, C->tf32)
    gemm_tf32<false,false,false,true,true><<<dim3((NH * QD) / BN, SQ / BM, 1), NTHR, SMEM_TOTAL>>>(
        p_qcn, Wq_d, Wq_d, p_q, NH * QD, RQ, RQ,
        RQ, NH * QD, NH * QD, NH * QD, 0, 0, 0, 1.0f);

    // 5) kv = ckvn @ Wkv_d                [1024, 32768]  (NN, cvt B, C->tf32)
    gemm_tf32<false,false,false,true,true><<<dim3((NH * KVD) / BN, SQ / BM, 1), NTHR, SMEM_TOTAL>>>(
        p_ckvn, Wkv_d, Wkv_d, p_kv, NH * KVD, RKV, RKV,
        RKV, NH * KVD, NH * KVD, NH * KVD, 0, 0, 0, 1.0f);

    // 6-7) rope
    rope_q_kernel<<<(SQ * NH * 32 + 255) / 256, 256>>>(p_q);
    rope_k_kernel<<<(SQ * 32 + 255) / 256, 256>>>(cache, p_kr);

    // 8..) attention, 32 heads per chunk — all tf32, cvt-free mainloops
    for (int ch = 0; ch < NCHUNK; ch++) {
        int h0 = ch * HCHUNK;

        // scores = scale * Q @ [Kn | kr]^T   (NT, dual-source K1=128, B2 unbatched)
        gemm_tf32<true,false,false,false,false><<<dim3(SQ / BN, SQ / BM, HCHUNK), NTHR, SMEM_TOTAL>>>(
            p_q + (size_t)h0 * QD,
            p_kv + (size_t)h0 * KVD,
            p_kr,
            p_sc,
            SQ, DQK, DNOPE,
            NH * QD, NH * KVD, DROPE, SQ,
            QD, KVD, (long long)SQ * SQ, scale);

        softmax_kernel<<<HCHUNK * SQ, 256>>>(p_sc);

        // att = probs @ V   (NN, V is strided slice of g_kv)
        gemm_tf32<false,false,false,false,true><<<dim3(DVV / BN, SQ / BM, HCHUNK), NTHR, SMEM_TOTAL>>>(
            p_sc,
            p_kv + (size_t)h0 * KVD + DNOPE,
            p_kv + (size_t)h0 * KVD + DNOPE,
            p_att + (size_t)h0 * DVV,
            DVV, SQ, SQ,
            SQ, NH * KVD, NH * KVD, NH * DVV,
            (long long)SQ * SQ, KVD, DVV, 1.0f);
    }

    // last) out = att @ Wo                [1024, 5120]  (NN, cvt B, fp32 out)
    gemm_tf32<false,false,false,true,false><<<dim3(HSZ / BN, SQ / BM, 1), NTHR, SMEM_TOTAL>>>(
        p_att, Wo, Wo, out, HSZ, NH * DVV, NH * DVV,
        NH * DVV, HSZ, HSZ, HSZ, 0, 0, 0, 1.0f);
}